// round 13
// baseline (speedup 1.0000x reference)
#include <cuda_runtime.h>
#include <cstdint>

// OR-tree reduction over rows of a (ROWS, 1024) float32 0/1 matrix.
// Reference pairwise-sum >= 0.5 tree == any(x >= 0.5) over the row.
//
// FINAL (= R6 configuration; best measured bench 6.08us; identical-code
// kernel times across R6/R11/R12: 5.86 / 6.18 / 5.79us -> +/-0.4us noise).
//
// Established model (R1-R12): DRAM scattered-line floor. All 65536 rows
// (4KB apart -> distinct DRAM pages/lines) must each be touched once;
// 65536 scattered 128B-line fetches cost ~5.8-6.2us on this chip,
// invariant to load count, MLP, occupancy, CTA count, L2 cache-hint
// policy, and address mapping (all tested, all within noise). Early-exit
// probing is the decisive algorithmic win: 8.4MB touched instead of the
// 256MB full read (R1 full-read style: 11.0us; naive estimate ~40us).
//
// Layout: 8 rows per warp. Lane L -> row (L>>2), float4 (L&3) within the
// probed 128B line at byte offset (row & 31)*128 (sweeps addr bits 7-11
// across the in-flight window for bank/channel spread). One LDG.128 per
// lane = 16 floats probed per row -> per-row unresolved prob 2^-16,
// expected ~1 rescue group grid-wide. Ballot combines each 4-lane group;
// lanes L%4==0 store 8 consecutive floats per warp (coalesced 32B).
// Rescue: warp-uniform batched full rescan (early exit per 128-float
// batch) -> correct for ANY input, including all-zero rows. rows % 8 == 0.

static constexpr int COLS = 1024;
static constexpr int F4_PER_ROW = COLS / 4; // 256
static constexpr unsigned FULL = 0xffffffffu;

__device__ __forceinline__ bool any_ge_half(const float4 v) {
    return (v.x >= 0.5f) | (v.y >= 0.5f) | (v.z >= 0.5f) | (v.w >= 0.5f);
}

__global__ void __launch_bounds__(256) vec_or_tree_kernel(
    const float4* __restrict__ x,
    float* __restrict__ out,
    int rows)
{
    const int warp = (blockIdx.x * blockDim.x + threadIdx.x) >> 5;
    const int lane = threadIdx.x & 31;
    const int rbase = warp * 8;
    if (rbase >= rows) return;

    const int rlocal = lane >> 2;   // 0..7: which of the 8 rows
    const int f4i    = lane & 3;    // 0..3: float4 within the probed line
    const int row    = rbase + rlocal;

    const float4* __restrict__ rp = x + (size_t)row * F4_PER_ROW;

    // De-aliased probe: 128B line at float4 index (row & 31) * 8.
    const int poff = (row & 31) * 8;
    const float4 v = rp[poff + f4i];
    bool fired = any_ge_half(v);

    // Combine within each 4-lane group via ballot.
    unsigned bal = __ballot_sync(FULL, fired);
    unsigned grp = (bal >> (lane & 28)) & 0xFu;
    bool done = (grp != 0);

    // Rescue (expected ~1 group in the whole grid): warp-uniform batched
    // full rescan of the row, early exit per 32-float4 batch.
    if (__any_sync(FULL, !done)) {
        #pragma unroll 1
        for (int base = 0; base < F4_PER_ROW; base += 32) {
            bool f = false;
            if (!done) {
                #pragma unroll
                for (int j = 0; j < 8; ++j) {
                    f |= any_ge_half(rp[base + f4i + 4 * j]);
                }
            }
            const unsigned b2 = __ballot_sync(FULL, f);
            grp |= (b2 >> (lane & 28)) & 0xFu;
            done = (grp != 0);
            if (__all_sync(FULL, done)) break;
        }
    }

    // Lanes 0,4,...,28 write 8 consecutive outputs (coalesced 32B).
    if ((lane & 3) == 0) out[row] = done ? 1.0f : 0.0f;
}

extern "C" void kernel_launch(void* const* d_in, const int* in_sizes, int n_in,
                              void* d_out, int out_size)
{
    const float4* x = (const float4*)d_in[0];
    float* out = (float*)d_out;
    const int rows = in_sizes[0] / COLS;   // 65536 (multiple of 8)

    const int threads = 256;                         // 8 warps/block
    const int rows_per_block = (threads / 32) * 8;   // 64
    const int blocks = (rows + rows_per_block - 1) / rows_per_block;  // 1024
    vec_or_tree_kernel<<<blocks, threads>>>(x, out, rows);
}